// round 16
// baseline (speedup 1.0000x reference)
#include <cuda_runtime.h>
#include <cuda_bf16.h>
#include <cuda_fp16.h>
#include <cstdint>

#define HEADS 16
#define DH    64
#define NB    2
#define T1    2048
#define T2    2048
#define HID   1024
#define BH    (NB*HEADS)

// ---------------- device scratch ----------------
__device__ __nv_bfloat16 g_qhi[(size_t)NB * T1 * HID];
__device__ __nv_bfloat16 g_qlo[(size_t)NB * T1 * HID];
__device__ __nv_bfloat16 g_khi[(size_t)NB * T2 * HID];
__device__ __nv_bfloat16 g_klo[(size_t)NB * T2 * HID];
__device__ __half        g_vf [(size_t)NB * T2 * HID];   // V, single fp16
__device__ __half        g_wf [(size_t)HID * HID];       // W, single fp16
__device__ __half        g_ch [(size_t)NB * T1 * HID];   // ctx, single fp16
__device__ int g_mask_flag;

// ---------------- helpers ----------------
__device__ __forceinline__ uint32_t smem_u32(const void* p) {
    uint32_t a;
    asm("{ .reg .u64 t; cvta.to.shared.u64 t, %1; cvt.u32.u64 %0, t; }" : "=r"(a) : "l"(p));
    return a;
}
__device__ __forceinline__ uint32_t sw128(uint32_t o) { return o ^ ((o >> 3) & 0x70); }

__device__ __forceinline__ float bf16r(float x) { return __bfloat162float(__float2bfloat16(x)); }
__device__ __forceinline__ uint32_t packbf2(float lo, float hi) {
    uint32_t r;
    asm("cvt.rn.bf16x2.f32 %0, %1, %2;" : "=r"(r) : "f"(hi), "f"(lo));
    return r;
}
__device__ __forceinline__ uint32_t packh2(float x, float y) {
    __half2 H = __floats2half2_rn(x, y);
    return *(uint32_t*)&H;
}

// fast 2^x for x <= 0, ~4e-5 rel error; all ops on rt-2 fixed pipes (no MUFU).
__device__ __forceinline__ float fexp2(float x) {
    float xc = fmaxf(x, -126.0f);
    int   ik = __float2int_rn(xc);
    float f  = xc - (float)ik;                 // f in [-0.5, 0.5]
    float p  = fmaf(f, 0.0096181f, 0.0555041f);
    p = fmaf(f, p, 0.2402265f);
    p = fmaf(f, p, 0.6931472f);
    p = fmaf(f, p, 1.0f);
    float sc = __int_as_float(ik * 8388608 + 0x3F800000);  // 2^ik
    return sc * p;
}

__device__ __forceinline__ void ldsm4(uint32_t& r0, uint32_t& r1, uint32_t& r2, uint32_t& r3, uint32_t a) {
    asm volatile("ldmatrix.sync.aligned.m8n8.x4.shared.b16 {%0,%1,%2,%3}, [%4];"
        : "=r"(r0), "=r"(r1), "=r"(r2), "=r"(r3) : "r"(a));
}
__device__ __forceinline__ void ldsm4t(uint32_t& r0, uint32_t& r1, uint32_t& r2, uint32_t& r3, uint32_t a) {
    asm volatile("ldmatrix.sync.aligned.m8n8.x4.trans.shared.b16 {%0,%1,%2,%3}, [%4];"
        : "=r"(r0), "=r"(r1), "=r"(r2), "=r"(r3) : "r"(a));
}
__device__ __forceinline__ void mmabf(float* c, const uint32_t* a, uint32_t b0, uint32_t b1) {
    asm volatile("mma.sync.aligned.m16n8k16.row.col.f32.bf16.bf16.f32 "
        "{%0,%1,%2,%3}, {%4,%5,%6,%7}, {%8,%9}, {%0,%1,%2,%3};"
        : "+f"(c[0]), "+f"(c[1]), "+f"(c[2]), "+f"(c[3])
        : "r"(a[0]), "r"(a[1]), "r"(a[2]), "r"(a[3]), "r"(b0), "r"(b1));
}
__device__ __forceinline__ void mmafp(float* c, const uint32_t* a, uint32_t b0, uint32_t b1) {
    asm volatile("mma.sync.aligned.m16n8k16.row.col.f32.f16.f16.f32 "
        "{%0,%1,%2,%3}, {%4,%5,%6,%7}, {%8,%9}, {%0,%1,%2,%3};"
        : "+f"(c[0]), "+f"(c[1]), "+f"(c[2]), "+f"(c[3])
        : "r"(a[0]), "r"(a[1]), "r"(a[2]), "r"(a[3]), "r"(b0), "r"(b1));
}

#define CP16(dst, src) asm volatile("cp.async.cg.shared.global [%0], [%1], 16;" :: "r"(dst), "l"(src) : "memory")
#define CP_COMMIT()    asm volatile("cp.async.commit_group;" ::: "memory")
#define CP_WAIT1()     asm volatile("cp.async.wait_group 1;" ::: "memory")
#define CP_WAIT0()     asm volatile("cp.async.wait_group 0;" ::: "memory")

// ---------------- fused prep: mask scan + q/k split + v/w convert ----------------
__global__ void zero_flag_k() { g_mask_flag = 0; }

__global__ __launch_bounds__(256) void prep_k(const float* __restrict__ q,
                                              const float* __restrict__ k,
                                              const float* __restrict__ v,
                                              const float* __restrict__ w,
                                              const float* __restrict__ mask)
{
    const int job = blockIdx.y;
    const int tid = blockIdx.x * 256 + threadIdx.x;
    const int nth = gridDim.x * 256;

    if (job == 0) {
        const float4* m4 = (const float4*)mask;
        const int n4 = NB * T2 * T2 / 4;
        bool nz = false;
        for (int i = tid; i < n4; i += nth) {
            float4 u = m4[i];
            nz |= (u.x != 0.f) || (u.y != 0.f) || (u.z != 0.f) || (u.w != 0.f);
        }
        if (__syncthreads_or(nz) && threadIdx.x == 0) atomicOr(&g_mask_flag, 1);
    } else if (job <= 2) {
        const float4* src = (const float4*)(job == 1 ? q : k);
        uint2* hi = (uint2*)(job == 1 ? g_qhi : g_khi);
        uint2* lo = (uint2*)(job == 1 ? g_qlo : g_klo);
        const int n4 = NB * T1 * HID / 4;
        for (int i = tid; i < n4; i += nth) {
            float4 u = src[i];
            float h0 = bf16r(u.x), h1 = bf16r(u.y), h2 = bf16r(u.z), h3 = bf16r(u.w);
            hi[i] = make_uint2(packbf2(h0, h1), packbf2(h2, h3));
            lo[i] = make_uint2(packbf2(u.x - h0, u.y - h1), packbf2(u.z - h2, u.w - h3));
        }
    } else if (job == 3) {
        const float4* src = (const float4*)v;
        uint2* dst = (uint2*)g_vf;
        const int n4 = NB * T2 * HID / 4;
        for (int i = tid; i < n4; i += nth) {
            float4 u = src[i];
            dst[i] = make_uint2(packh2(u.x, u.y), packh2(u.z, u.w));
        }
    } else {
        const float4* src = (const float4*)w;
        uint2* dst = (uint2*)g_wf;
        const int n4 = HID * HID / 4;
        for (int i = tid; i < n4; i += nth) {
            float4 u = src[i];
            dst[i] = make_uint2(packh2(u.x, u.y), packh2(u.z, u.w));
        }
    }
}

// ---------------- attention (R14 structure; S = bf16x3, PV = fp16x1; fexp2 softmax) ----------------
#define AT_BUF   24576
#define AO_KH    0
#define AO_KL    8192
#define AO_VF    16384
#define ATT_SMEM (3 * AT_BUF + 1024)

__device__ __forceinline__ void issue_tile(uint32_t sbuf, int k0, int tid,
    const __nv_bfloat16* khg, const __nv_bfloat16* klg, const __half* vfg)
{
    #pragma unroll
    for (int j = 0; j < 2; j++) {
        int i = tid * 2 + j;
        int row = i >> 3, seg = i & 7;
        uint32_t dsw = sw128((uint32_t)(row * 128 + seg * 16));
        size_t roff = (size_t)(k0 + row) * HID + seg * 8;
        CP16(sbuf + AO_KH + dsw, khg + roff);
        CP16(sbuf + AO_KL + dsw, klg + roff);
        CP16(sbuf + AO_VF + dsw, vfg + roff);
    }
}

__global__ __launch_bounds__(256, 2) void attn_tc(const float* __restrict__ mask)
{
    extern __shared__ char smraw[];
    uint32_t sb0 = smem_u32(smraw);
    uint32_t pad = (1024u - (sb0 & 1023u)) & 1023u;
    char* smp = smraw + pad;
    uint32_t sb = sb0 + pad;

    const int tid = threadIdx.x;
    const int w = tid >> 5, l = tid & 31;
    const int bh = blockIdx.y, b = bh >> 4, h = bh & 15;
    const int q0 = blockIdx.x * 128;
    const float L2E = 1.4426950408889634f;

    const __nv_bfloat16* khg = g_khi + (size_t)b * T2 * HID + h * DH;
    const __nv_bfloat16* klg = g_klo + (size_t)b * T2 * HID + h * DH;
    const __half*        vfg = g_vf  + (size_t)b * T2 * HID + h * DH;

    // ---- load Q fragments (persist in registers), staged through buf0 ----
    uint32_t qh_[4][4], ql_[4][4];
    {
        const __nv_bfloat16* qhg = g_qhi + ((size_t)b * T1 + q0) * HID + h * DH;
        const __nv_bfloat16* qlg = g_qlo + ((size_t)b * T1 + q0) * HID + h * DH;
        const uint32_t qrow = (uint32_t)(16 * w + (l & 15));
        #pragma unroll
        for (int pass = 0; pass < 2; pass++) {
            const __nv_bfloat16* src = pass ? qlg : qhg;
            #pragma unroll
            for (int j = 0; j < 4; j++) {
                int i = tid * 4 + j;
                int row = i >> 3, seg = i & 7;
                *(uint4*)(smp + sw128((uint32_t)(row * 128 + seg * 16))) =
                    *(const uint4*)(src + (size_t)row * HID + seg * 8);
            }
            __syncthreads();
            #pragma unroll
            for (int st = 0; st < 4; st++) {
                uint32_t a = sb + sw128(qrow * 128 + (uint32_t)(2 * st + (l >> 4)) * 16);
                if (pass == 0) ldsm4(qh_[st][0], qh_[st][1], qh_[st][2], qh_[st][3], a);
                else           ldsm4(ql_[st][0], ql_[st][1], ql_[st][2], ql_[st][3], a);
            }
            __syncthreads();
        }
    }

    // kick off tiles 0,1 into bufs 0,1
    issue_tile(sb, 0, tid, khg, klg, vfg);
    CP_COMMIT();
    issue_tile(sb + AT_BUF, 64, tid, khg, klg, vfg);
    CP_COMMIT();

    const bool use_mask = (g_mask_flag != 0);
    const float* mr0 = mask + ((size_t)b * T2 + (q0 + 16 * w + (l >> 2))) * T2;
    const float* mr1 = mr0 + (size_t)8 * T2;

    const uint32_t krow = (uint32_t)((l & 7) + ((l & 16) >> 1)); // + 16*g
    const uint32_t kseg = (uint32_t)((l >> 3) & 1);              // + 2*st
    const uint32_t vrow = (uint32_t)((l & 7) + (l & 8));         // + 16*st
    const uint32_t vseg = (uint32_t)(l >> 4);                    // + 2*g

    float o_[8][4];
    #pragma unroll
    for (int i = 0; i < 8; i++)
        #pragma unroll
        for (int j = 0; j < 4; j++) o_[i][j] = 0.f;
    float m0 = -1e30f, m1 = -1e30f, l0 = 0.f, l1 = 0.f;

    int ci = 0, ii = 2;   // current buf, issue buf (rotating mod 3)
    for (int kt = 0; kt < 32; kt++) {
        if (kt == 31) { CP_WAIT0(); } else { CP_WAIT1(); }
        __syncthreads();
        if (kt + 2 < 32) {
            issue_tile(sb + (uint32_t)ii * AT_BUF, (kt + 2) * 64, tid, khg, klg, vfg);
            CP_COMMIT();
        }
        uint32_t cur = sb + (uint32_t)ci * AT_BUF;
        ci = (ci == 2) ? 0 : ci + 1;
        ii = (ii == 2) ? 0 : ii + 1;

        // ---- S = Qhi*Khi + Qhi*Klo + Qlo*Khi (bf16 x3) ----
        float s_[8][4];
        #pragma unroll
        for (int i = 0; i < 8; i++)
            #pragma unroll
            for (int j = 0; j < 4; j++) s_[i][j] = 0.f;

        #pragma unroll
        for (int st = 0; st < 4; st++) {
            #pragma unroll
            for (int g = 0; g < 4; g++) {
                uint32_t off = sw128((uint32_t)((16 * g + krow) * 128 + (2 * st + kseg) * 16));
                uint32_t b0, b1, b2, b3;
                ldsm4(b0, b1, b2, b3, cur + AO_KH + off);
                mmabf(s_[2 * g], qh_[st], b0, b1);
                mmabf(s_[2 * g + 1], qh_[st], b2, b3);
                mmabf(s_[2 * g], ql_[st], b0, b1);
                mmabf(s_[2 * g + 1], ql_[st], b2, b3);
                uint32_t c0, c1, c2, c3;
                ldsm4(c0, c1, c2, c3, cur + AO_KL + off);
                mmabf(s_[2 * g], qh_[st], c0, c1);
                mmabf(s_[2 * g + 1], qh_[st], c2, c3);
            }
        }

        if (use_mask) {
            int k0 = kt * 64;
            #pragma unroll
            for (int nf = 0; nf < 8; nf++) {
                float2 a = *(const float2*)(mr0 + k0 + 8 * nf + 2 * (l & 3));
                float2 c = *(const float2*)(mr1 + k0 + 8 * nf + 2 * (l & 3));
                s_[nf][0] += a.x; s_[nf][1] += a.y;
                s_[nf][2] += c.x; s_[nf][3] += c.y;
            }
        }

        // ---- online softmax: tree max ----
        float a0 = fmaxf(s_[0][0], s_[0][1]), a1 = fmaxf(s_[1][0], s_[1][1]);
        float a2 = fmaxf(s_[2][0], s_[2][1]), a3 = fmaxf(s_[3][0], s_[3][1]);
        float a4 = fmaxf(s_[4][0], s_[4][1]), a5 = fmaxf(s_[5][0], s_[5][1]);
        float a6 = fmaxf(s_[6][0], s_[6][1]), a7 = fmaxf(s_[7][0], s_[7][1]);
        float mt0 = fmaxf(fmaxf(fmaxf(a0, a1), fmaxf(a2, a3)),
                          fmaxf(fmaxf(a4, a5), fmaxf(a6, a7)));
        float b0_ = fmaxf(s_[0][2], s_[0][3]), b1_ = fmaxf(s_[1][2], s_[1][3]);
        float b2_ = fmaxf(s_[2][2], s_[2][3]), b3_ = fmaxf(s_[3][2], s_[3][3]);
        float b4_ = fmaxf(s_[4][2], s_[4][3]), b5_ = fmaxf(s_[5][2], s_[5][3]);
        float b6_ = fmaxf(s_[6][2], s_[6][3]), b7_ = fmaxf(s_[7][2], s_[7][3]);
        float mt1 = fmaxf(fmaxf(fmaxf(b0_, b1_), fmaxf(b2_, b3_)),
                          fmaxf(fmaxf(b4_, b5_), fmaxf(b6_, b7_)));
        mt0 = fmaxf(mt0, __shfl_xor_sync(0xffffffffu, mt0, 1));
        mt0 = fmaxf(mt0, __shfl_xor_sync(0xffffffffu, mt0, 2));
        mt1 = fmaxf(mt1, __shfl_xor_sync(0xffffffffu, mt1, 1));
        mt1 = fmaxf(mt1, __shfl_xor_sync(0xffffffffu, mt1, 2));
        float nm0 = fmaxf(m0, mt0), nm1 = fmaxf(m1, mt1);
        bool chg = (nm0 != m0) | (nm1 != m1);
        float cr0 = 1.0f, cr1 = 1.0f;
        if (__any_sync(0xffffffffu, chg)) {
            cr0 = fexp2((m0 - nm0) * L2E);
            cr1 = fexp2((m1 - nm1) * L2E);
            // o-rescale (only when some row's max moved)
            #pragma unroll
            for (int nf = 0; nf < 8; nf++) {
                o_[nf][0] *= cr0; o_[nf][1] *= cr0;
                o_[nf][2] *= cr1; o_[nf][3] *= cr1;
            }
        }
        m0 = nm0; m1 = nm1;
        float nmL0 = nm0 * L2E, nmL1 = nm1 * L2E;

        #pragma unroll
        for (int nf = 0; nf < 8; nf++) {
            s_[nf][0] = fexp2(fmaf(s_[nf][0], L2E, -nmL0));
            s_[nf][1] = fexp2(fmaf(s_[nf][1], L2E, -nmL0));
            s_[nf][2] = fexp2(fmaf(s_[nf][2], L2E, -nmL1));
            s_[nf][3] = fexp2(fmaf(s_[nf][3], L2E, -nmL1));
        }

        // per-lane partial sums (quad-reduce deferred to epilogue; cr is quad-uniform)
        float u0 = (s_[0][0] + s_[0][1]) + (s_[1][0] + s_[1][1]);
        float u1 = (s_[2][0] + s_[2][1]) + (s_[3][0] + s_[3][1]);
        float u2 = (s_[4][0] + s_[4][1]) + (s_[5][0] + s_[5][1]);
        float u3 = (s_[6][0] + s_[6][1]) + (s_[7][0] + s_[7][1]);
        float w0 = (s_[0][2] + s_[0][3]) + (s_[1][2] + s_[1][3]);
        float w1 = (s_[2][2] + s_[2][3]) + (s_[3][2] + s_[3][3]);
        float w2 = (s_[4][2] + s_[4][3]) + (s_[5][2] + s_[5][3]);
        float w3 = (s_[6][2] + s_[6][3]) + (s_[7][2] + s_[7][3]);
        l0 = l0 * cr0 + ((u0 + u1) + (u2 + u3));
        l1 = l1 * cr1 + ((w0 + w1) + (w2 + w3));

        // ---- pack P -> fp16 A fragments ----
        uint32_t ph_[4][4];
        #pragma unroll
        for (int st = 0; st < 4; st++) {
            ph_[st][0] = packh2(s_[2 * st][0],     s_[2 * st][1]);
            ph_[st][1] = packh2(s_[2 * st][2],     s_[2 * st][3]);
            ph_[st][2] = packh2(s_[2 * st + 1][0], s_[2 * st + 1][1]);
            ph_[st][3] = packh2(s_[2 * st + 1][2], s_[2 * st + 1][3]);
        }

        // ---- O += P*V (fp16 x1) ----
        #pragma unroll
        for (int st = 0; st < 4; st++) {
            #pragma unroll
            for (int g = 0; g < 4; g++) {
                uint32_t off = sw128((uint32_t)((16 * st + vrow) * 128 + (2 * g + vseg) * 16));
                uint32_t b0, b1, b2, b3;
                ldsm4t(b0, b1, b2, b3, cur + AO_VF + off);
                mmafp(o_[2 * g], ph_[st], b0, b1);
                mmafp(o_[2 * g + 1], ph_[st], b2, b3);
            }
        }
    }

    // ---- epilogue: quad-reduce l, normalize, write fp16 ctx ----
    l0 += __shfl_xor_sync(0xffffffffu, l0, 1);
    l0 += __shfl_xor_sync(0xffffffffu, l0, 2);
    l1 += __shfl_xor_sync(0xffffffffu, l1, 1);
    l1 += __shfl_xor_sync(0xffffffffu, l1, 2);
    float inv0 = 1.0f / l0, inv1 = 1.0f / l1;
    int r0 = q0 + 16 * w + (l >> 2);
    size_t base0 = ((size_t)b * T1 + r0) * HID + h * DH;
    size_t base1 = base0 + (size_t)8 * HID;
    #pragma unroll
    for (int nf = 0; nf < 8; nf++) {
        int col = 8 * nf + 2 * (l & 3);
        *(uint32_t*)(g_ch + base0 + col) = packh2(o_[nf][0] * inv0, o_[nf][1] * inv0);
        *(uint32_t*)(g_ch + base1 + col) = packh2(o_[nf][2] * inv1, o_[nf][3] * inv1);
    }
}

// ---------------- proj (R14 version): 128x128 CTA, 32x64 warp tiles, 3-stage ----------------
#define PB_A  0
#define PB_W  16384
#define PB_SZ 32768
#define PROJ_SMEM (3 * PB_SZ + 1024)

__device__ __forceinline__ void proj_issue(uint32_t sbuf, int r0c, int n0, int e0, int tid)
{
    #pragma unroll
    for (int j = 0; j < 4; j++) {
        int i = tid * 4 + j;
        int row = i >> 3, seg = i & 7;
        uint32_t dsw = sw128((uint32_t)(row * 128 + seg * 16));
        size_t roff = (size_t)(r0c + row) * HID + e0 + seg * 8;
        CP16(sbuf + PB_A + dsw, g_ch + roff);
    }
    #pragma unroll
    for (int j = 0; j < 4; j++) {
        int i = tid * 4 + j;
        int row = i >> 3, seg = i & 7;
        uint32_t dsw = sw128((uint32_t)(row * 128 + seg * 16));
        size_t roff = (size_t)(n0 + row) * HID + e0 + seg * 8;
        CP16(sbuf + PB_W + dsw, g_wf + roff);
    }
}

__global__ __launch_bounds__(256, 2) void proj_tc(const float* __restrict__ bias,
                                                  float* __restrict__ out)
{
    extern __shared__ char smraw[];
    uint32_t sb0 = smem_u32(smraw);
    uint32_t pad = (1024u - (sb0 & 1023u)) & 1023u;
    uint32_t sb = sb0 + pad;

    const int tid = threadIdx.x;
    const int w = tid >> 5, l = tid & 31;
    const int wr = w >> 1, wc = w & 1;           // warp tile: rows 32*wr, cols 64*wc
    const int r0c = blockIdx.x * 128, n0 = blockIdx.y * 128;

    const uint32_t aseg = (uint32_t)(l >> 4);
    const uint32_t krow = (uint32_t)((l & 7) + ((l & 16) >> 1));
    const uint32_t kseg = (uint32_t)((l >> 3) & 1);

    float acc[16][4];   // [mf*8 + nf][4]
    #pragma unroll
    for (int i = 0; i < 16; i++)
        #pragma unroll
        for (int j = 0; j < 4; j++) acc[i][j] = 0.f;

    proj_issue(sb, r0c, n0, 0, tid);
    CP_COMMIT();
    proj_issue(sb + PB_SZ, r0c, n0, 64, tid);
    CP_COMMIT();

    int cb = 0;
    for (int c = 0; c < 16; c++) {
        CP_WAIT1();
        __syncthreads();
        if (c + 2 < 16) {
            int ib = cb + 2; if (ib >= 3) ib -= 3;
            proj_issue(sb + (uint32_t)ib * PB_SZ, r0c, n0, (c + 2) * 64, tid);
            CP_COMMIT();
        }
        uint32_t cur = sb + (uint32_t)cb * PB_SZ;
        cb = (cb == 2) ? 0 : cb + 1;

        uint32_t a_[2][4][4];
        #pragma unroll
        for (int mf = 0; mf < 2; mf++) {
            uint32_t arow = (uint32_t)(32 * wr + 16 * mf + (l & 15));
            #pragma unroll
            for (int st = 0; st < 4; st++) {
                uint32_t a = cur + PB_A + sw128(arow * 128 + (uint32_t)(2 * st + aseg) * 16);
                ldsm4(a_[mf][st][0], a_[mf][st][1], a_[mf][st][2], a_[mf][st][3], a);
            }
        }
        #pragma unroll
        for (int st = 0; st < 4; st++) {
            #pragma unroll
            for (int g = 0; g < 4; g++) {
                uint32_t wrow = (uint32_t)(64 * wc + 16 * g) + krow;
                uint32_t off = sw128(wrow * 128 + (uint32_t)(2 * st + kseg) * 16);
                uint32_t b0, b1, b2, b3;
                ldsm4(b0, b1, b2, b3, cur + PB_W + off);
                mmafp(acc[2 * g],      a_[0][st], b0, b1);
                mmafp(acc[2 * g + 1],  a_[0][st], b2, b3);
                mmafp(acc[8 + 2 * g],     a_[1][st], b0, b1);
                mmafp(acc[8 + 2 * g + 1], a_[1][st], b2, b3);
            }
        }
    }

    // epilogue: +bias, relu
    #pragma unroll
    for (int mf = 0; mf < 2; mf++) {
        int row0 = r0c + 32 * wr + 16 * mf + (l >> 2);
        #pragma unroll
        for (int nf = 0; nf < 8; nf++) {
            int col = n0 + 64 * wc + 8 * nf + 2 * (l & 3);
            float bx = bias[col], by = bias[col + 1];
            const float* a = acc[mf * 8 + nf];
            float2 t0 = make_float2(fmaxf(a[0] + bx, 0.f), fmaxf(a[1] + by, 0.f));
            float2 t1 = make_float2(fmaxf(a[2] + bx, 0.f), fmaxf(a[3] + by, 0.f));
            *(float2*)(out + (size_t)row0 * HID + col) = t0;
            *(float2*)(out + (size_t)(row0 + 8) * HID + col) = t1;
        }
    }
}

// ---------------- launch ----------------
extern "C" void kernel_launch(void* const* d_in, const int* in_sizes, int n_in,
                              void* d_out, int out_size)
{
    const float* q    = (const float*)d_in[0];
    const float* ek   = (const float*)d_in[1];
    const float* ev   = (const float*)d_in[2];
    const float* mask = (const float*)d_in[3];
    const float* wo_w = (const float*)d_in[4];
    const float* wo_b = (const float*)d_in[5];
    float* out = (float*)d_out;

    cudaFuncSetAttribute(attn_tc, cudaFuncAttributeMaxDynamicSharedMemorySize, ATT_SMEM);
    cudaFuncSetAttribute(proj_tc, cudaFuncAttributeMaxDynamicSharedMemorySize, PROJ_SMEM);

    zero_flag_k<<<1, 1>>>();

    dim3 gPr(512, 5);
    prep_k<<<gPr, 256>>>(q, ek, ev, wo_w, mask);

    dim3 gA(T1 / 128, BH);
    attn_tc<<<gA, 256, ATT_SMEM>>>(mask);

    dim3 gP(NB * T1 / 128, HID / 128);
    proj_tc<<<gP, 256, PROJ_SMEM>>>(wo_b, out);
}

// round 17
// speedup vs baseline: 1.1302x; 1.1302x over previous
#include <cuda_runtime.h>
#include <cuda_bf16.h>
#include <cuda_fp16.h>
#include <cstdint>

#define HEADS 16
#define DH    64
#define NB    2
#define T1    2048
#define T2    2048
#define HID   1024
#define BH    (NB*HEADS)

// ---------------- device scratch ----------------
__device__ __nv_bfloat16 g_qhi[(size_t)NB * T1 * HID];
__device__ __nv_bfloat16 g_qlo[(size_t)NB * T1 * HID];
__device__ __nv_bfloat16 g_khi[(size_t)NB * T2 * HID];
__device__ __nv_bfloat16 g_klo[(size_t)NB * T2 * HID];
__device__ __half        g_vf [(size_t)NB * T2 * HID];   // V, single fp16
__device__ __half        g_wf [(size_t)HID * HID];       // W, single fp16
__device__ __half        g_ch [(size_t)NB * T1 * HID];   // ctx, single fp16
__device__ int g_mask_flag;

// ---------------- helpers ----------------
__device__ __forceinline__ uint32_t smem_u32(const void* p) {
    uint32_t a;
    asm("{ .reg .u64 t; cvta.to.shared.u64 t, %1; cvt.u32.u64 %0, t; }" : "=r"(a) : "l"(p));
    return a;
}
__device__ __forceinline__ uint32_t sw128(uint32_t o) { return o ^ ((o >> 3) & 0x70); }

__device__ __forceinline__ float bf16r(float x) { return __bfloat162float(__float2bfloat16(x)); }
__device__ __forceinline__ uint32_t packbf2(float lo, float hi) {
    uint32_t r;
    asm("cvt.rn.bf16x2.f32 %0, %1, %2;" : "=r"(r) : "f"(hi), "f"(lo));
    return r;
}
__device__ __forceinline__ uint32_t packh2(float x, float y) {
    __half2 H = __floats2half2_rn(x, y);
    return *(uint32_t*)&H;
}

__device__ __forceinline__ void ldsm4(uint32_t& r0, uint32_t& r1, uint32_t& r2, uint32_t& r3, uint32_t a) {
    asm volatile("ldmatrix.sync.aligned.m8n8.x4.shared.b16 {%0,%1,%2,%3}, [%4];"
        : "=r"(r0), "=r"(r1), "=r"(r2), "=r"(r3) : "r"(a));
}
__device__ __forceinline__ void ldsm4t(uint32_t& r0, uint32_t& r1, uint32_t& r2, uint32_t& r3, uint32_t a) {
    asm volatile("ldmatrix.sync.aligned.m8n8.x4.trans.shared.b16 {%0,%1,%2,%3}, [%4];"
        : "=r"(r0), "=r"(r1), "=r"(r2), "=r"(r3) : "r"(a));
}
__device__ __forceinline__ void mmabf(float* c, const uint32_t* a, uint32_t b0, uint32_t b1) {
    asm volatile("mma.sync.aligned.m16n8k16.row.col.f32.bf16.bf16.f32 "
        "{%0,%1,%2,%3}, {%4,%5,%6,%7}, {%8,%9}, {%0,%1,%2,%3};"
        : "+f"(c[0]), "+f"(c[1]), "+f"(c[2]), "+f"(c[3])
        : "r"(a[0]), "r"(a[1]), "r"(a[2]), "r"(a[3]), "r"(b0), "r"(b1));
}
__device__ __forceinline__ void mmafp(float* c, const uint32_t* a, uint32_t b0, uint32_t b1) {
    asm volatile("mma.sync.aligned.m16n8k16.row.col.f32.f16.f16.f32 "
        "{%0,%1,%2,%3}, {%4,%5,%6,%7}, {%8,%9}, {%0,%1,%2,%3};"
        : "+f"(c[0]), "+f"(c[1]), "+f"(c[2]), "+f"(c[3])
        : "r"(a[0]), "r"(a[1]), "r"(a[2]), "r"(a[3]), "r"(b0), "r"(b1));
}

#define CP16(dst, src) asm volatile("cp.async.cg.shared.global [%0], [%1], 16;" :: "r"(dst), "l"(src) : "memory")
#define CP_COMMIT()    asm volatile("cp.async.commit_group;" ::: "memory")
#define CP_WAIT1()     asm volatile("cp.async.wait_group 1;" ::: "memory")
#define CP_WAIT0()     asm volatile("cp.async.wait_group 0;" ::: "memory")

// ---------------- fused prep: mask scan + q/k split + v/w convert ----------------
__global__ void zero_flag_k() { g_mask_flag = 0; }

__global__ __launch_bounds__(256) void prep_k(const float* __restrict__ q,
                                              const float* __restrict__ k,
                                              const float* __restrict__ v,
                                              const float* __restrict__ w,
                                              const float* __restrict__ mask)
{
    const int job = blockIdx.y;
    const int tid = blockIdx.x * 256 + threadIdx.x;
    const int nth = gridDim.x * 256;

    if (job == 0) {
        const float4* m4 = (const float4*)mask;
        const int n4 = NB * T2 * T2 / 4;
        bool nz = false;
        for (int i = tid; i < n4; i += nth) {
            float4 u = m4[i];
            nz |= (u.x != 0.f) || (u.y != 0.f) || (u.z != 0.f) || (u.w != 0.f);
        }
        if (__syncthreads_or(nz) && threadIdx.x == 0) atomicOr(&g_mask_flag, 1);
    } else if (job <= 2) {
        const float4* src = (const float4*)(job == 1 ? q : k);
        uint2* hi = (uint2*)(job == 1 ? g_qhi : g_khi);
        uint2* lo = (uint2*)(job == 1 ? g_qlo : g_klo);
        const int n4 = NB * T1 * HID / 4;
        for (int i = tid; i < n4; i += nth) {
            float4 u = src[i];
            float h0 = bf16r(u.x), h1 = bf16r(u.y), h2 = bf16r(u.z), h3 = bf16r(u.w);
            hi[i] = make_uint2(packbf2(h0, h1), packbf2(h2, h3));
            lo[i] = make_uint2(packbf2(u.x - h0, u.y - h1), packbf2(u.z - h2, u.w - h3));
        }
    } else if (job == 3) {
        const float4* src = (const float4*)v;
        uint2* dst = (uint2*)g_vf;
        const int n4 = NB * T2 * HID / 4;
        for (int i = tid; i < n4; i += nth) {
            float4 u = src[i];
            dst[i] = make_uint2(packh2(u.x, u.y), packh2(u.z, u.w));
        }
    } else {
        const float4* src = (const float4*)w;
        uint2* dst = (uint2*)g_wf;
        const int n4 = HID * HID / 4;
        for (int i = tid; i < n4; i += nth) {
            float4 u = src[i];
            dst[i] = make_uint2(packh2(u.x, u.y), packh2(u.z, u.w));
        }
    }
}

// ---------------- attention (R14 exact: S = bf16x3, PV = fp16x1; 64-row tiles, 3 buffers) ----------------
#define AT_BUF   24576
#define AO_KH    0
#define AO_KL    8192
#define AO_VF    16384
#define ATT_SMEM (3 * AT_BUF + 1024)

__device__ __forceinline__ void issue_tile(uint32_t sbuf, int k0, int tid,
    const __nv_bfloat16* khg, const __nv_bfloat16* klg, const __half* vfg)
{
    #pragma unroll
    for (int j = 0; j < 2; j++) {
        int i = tid * 2 + j;
        int row = i >> 3, seg = i & 7;
        uint32_t dsw = sw128((uint32_t)(row * 128 + seg * 16));
        size_t roff = (size_t)(k0 + row) * HID + seg * 8;
        CP16(sbuf + AO_KH + dsw, khg + roff);
        CP16(sbuf + AO_KL + dsw, klg + roff);
        CP16(sbuf + AO_VF + dsw, vfg + roff);
    }
}

__global__ __launch_bounds__(256, 2) void attn_tc(const float* __restrict__ mask)
{
    extern __shared__ char smraw[];
    uint32_t sb0 = smem_u32(smraw);
    uint32_t pad = (1024u - (sb0 & 1023u)) & 1023u;
    char* smp = smraw + pad;
    uint32_t sb = sb0 + pad;

    const int tid = threadIdx.x;
    const int w = tid >> 5, l = tid & 31;
    const int bh = blockIdx.y, b = bh >> 4, h = bh & 15;
    const int q0 = blockIdx.x * 128;
    const float L2E = 1.4426950408889634f;

    const __nv_bfloat16* khg = g_khi + (size_t)b * T2 * HID + h * DH;
    const __nv_bfloat16* klg = g_klo + (size_t)b * T2 * HID + h * DH;
    const __half*        vfg = g_vf  + (size_t)b * T2 * HID + h * DH;

    // ---- load Q fragments (persist in registers), staged through buf0 ----
    uint32_t qh_[4][4], ql_[4][4];
    {
        const __nv_bfloat16* qhg = g_qhi + ((size_t)b * T1 + q0) * HID + h * DH;
        const __nv_bfloat16* qlg = g_qlo + ((size_t)b * T1 + q0) * HID + h * DH;
        const uint32_t qrow = (uint32_t)(16 * w + (l & 15));
        #pragma unroll
        for (int pass = 0; pass < 2; pass++) {
            const __nv_bfloat16* src = pass ? qlg : qhg;
            #pragma unroll
            for (int j = 0; j < 4; j++) {
                int i = tid * 4 + j;
                int row = i >> 3, seg = i & 7;
                *(uint4*)(smp + sw128((uint32_t)(row * 128 + seg * 16))) =
                    *(const uint4*)(src + (size_t)row * HID + seg * 8);
            }
            __syncthreads();
            #pragma unroll
            for (int st = 0; st < 4; st++) {
                uint32_t a = sb + sw128(qrow * 128 + (uint32_t)(2 * st + (l >> 4)) * 16);
                if (pass == 0) ldsm4(qh_[st][0], qh_[st][1], qh_[st][2], qh_[st][3], a);
                else           ldsm4(ql_[st][0], ql_[st][1], ql_[st][2], ql_[st][3], a);
            }
            __syncthreads();
        }
    }

    // kick off tiles 0,1 into bufs 0,1
    issue_tile(sb, 0, tid, khg, klg, vfg);
    CP_COMMIT();
    issue_tile(sb + AT_BUF, 64, tid, khg, klg, vfg);
    CP_COMMIT();

    const bool use_mask = (g_mask_flag != 0);
    const float* mr0 = mask + ((size_t)b * T2 + (q0 + 16 * w + (l >> 2))) * T2;
    const float* mr1 = mr0 + (size_t)8 * T2;

    const uint32_t krow = (uint32_t)((l & 7) + ((l & 16) >> 1)); // + 16*g
    const uint32_t kseg = (uint32_t)((l >> 3) & 1);              // + 2*st
    const uint32_t vrow = (uint32_t)((l & 7) + (l & 8));         // + 16*st
    const uint32_t vseg = (uint32_t)(l >> 4);                    // + 2*g

    float o_[8][4];
    #pragma unroll
    for (int i = 0; i < 8; i++)
        #pragma unroll
        for (int j = 0; j < 4; j++) o_[i][j] = 0.f;
    float m0 = -1e30f, m1 = -1e30f, l0 = 0.f, l1 = 0.f;

    int ci = 0, ii = 2;   // current buf, issue buf (rotating mod 3)
    for (int kt = 0; kt < 32; kt++) {
        if (kt == 31) { CP_WAIT0(); } else { CP_WAIT1(); }
        __syncthreads();
        if (kt + 2 < 32) {
            issue_tile(sb + (uint32_t)ii * AT_BUF, (kt + 2) * 64, tid, khg, klg, vfg);
            CP_COMMIT();
        }
        uint32_t cur = sb + (uint32_t)ci * AT_BUF;
        ci = (ci == 2) ? 0 : ci + 1;
        ii = (ii == 2) ? 0 : ii + 1;

        // ---- S = Qhi*Khi + Qhi*Klo + Qlo*Khi (bf16 x3) ----
        float s_[8][4];
        #pragma unroll
        for (int i = 0; i < 8; i++)
            #pragma unroll
            for (int j = 0; j < 4; j++) s_[i][j] = 0.f;

        #pragma unroll
        for (int st = 0; st < 4; st++) {
            #pragma unroll
            for (int g = 0; g < 4; g++) {
                uint32_t off = sw128((uint32_t)((16 * g + krow) * 128 + (2 * st + kseg) * 16));
                uint32_t b0, b1, b2, b3;
                ldsm4(b0, b1, b2, b3, cur + AO_KH + off);
                mmabf(s_[2 * g], qh_[st], b0, b1);
                mmabf(s_[2 * g + 1], qh_[st], b2, b3);
                mmabf(s_[2 * g], ql_[st], b0, b1);
                mmabf(s_[2 * g + 1], ql_[st], b2, b3);
                uint32_t c0, c1, c2, c3;
                ldsm4(c0, c1, c2, c3, cur + AO_KL + off);
                mmabf(s_[2 * g], qh_[st], c0, c1);
                mmabf(s_[2 * g + 1], qh_[st], c2, c3);
            }
        }

        if (use_mask) {
            int k0 = kt * 64;
            #pragma unroll
            for (int nf = 0; nf < 8; nf++) {
                float2 a = *(const float2*)(mr0 + k0 + 8 * nf + 2 * (l & 3));
                float2 c = *(const float2*)(mr1 + k0 + 8 * nf + 2 * (l & 3));
                s_[nf][0] += a.x; s_[nf][1] += a.y;
                s_[nf][2] += c.x; s_[nf][3] += c.y;
            }
        }

        // ---- online softmax: tree max ----
        float a0 = fmaxf(s_[0][0], s_[0][1]), a1 = fmaxf(s_[1][0], s_[1][1]);
        float a2 = fmaxf(s_[2][0], s_[2][1]), a3 = fmaxf(s_[3][0], s_[3][1]);
        float a4 = fmaxf(s_[4][0], s_[4][1]), a5 = fmaxf(s_[5][0], s_[5][1]);
        float a6 = fmaxf(s_[6][0], s_[6][1]), a7 = fmaxf(s_[7][0], s_[7][1]);
        float mt0 = fmaxf(fmaxf(fmaxf(a0, a1), fmaxf(a2, a3)),
                          fmaxf(fmaxf(a4, a5), fmaxf(a6, a7)));
        float b0_ = fmaxf(s_[0][2], s_[0][3]), b1_ = fmaxf(s_[1][2], s_[1][3]);
        float b2_ = fmaxf(s_[2][2], s_[2][3]), b3_ = fmaxf(s_[3][2], s_[3][3]);
        float b4_ = fmaxf(s_[4][2], s_[4][3]), b5_ = fmaxf(s_[5][2], s_[5][3]);
        float b6_ = fmaxf(s_[6][2], s_[6][3]), b7_ = fmaxf(s_[7][2], s_[7][3]);
        float mt1 = fmaxf(fmaxf(fmaxf(b0_, b1_), fmaxf(b2_, b3_)),
                          fmaxf(fmaxf(b4_, b5_), fmaxf(b6_, b7_)));
        mt0 = fmaxf(mt0, __shfl_xor_sync(0xffffffffu, mt0, 1));
        mt0 = fmaxf(mt0, __shfl_xor_sync(0xffffffffu, mt0, 2));
        mt1 = fmaxf(mt1, __shfl_xor_sync(0xffffffffu, mt1, 1));
        mt1 = fmaxf(mt1, __shfl_xor_sync(0xffffffffu, mt1, 2));
        float nm0 = fmaxf(m0, mt0), nm1 = fmaxf(m1, mt1);
        float cr0 = exp2f((m0 - nm0) * L2E);
        float cr1 = exp2f((m1 - nm1) * L2E);
        m0 = nm0; m1 = nm1;
        float nmL0 = nm0 * L2E, nmL1 = nm1 * L2E;

        // o-rescale (independent FMULs interleave with the MUFU burst below)
        #pragma unroll
        for (int nf = 0; nf < 8; nf++) {
            o_[nf][0] *= cr0; o_[nf][1] *= cr0;
            o_[nf][2] *= cr1; o_[nf][3] *= cr1;
        }

        #pragma unroll
        for (int nf = 0; nf < 8; nf++) {
            s_[nf][0] = exp2f(fmaf(s_[nf][0], L2E, -nmL0));
            s_[nf][1] = exp2f(fmaf(s_[nf][1], L2E, -nmL0));
            s_[nf][2] = exp2f(fmaf(s_[nf][2], L2E, -nmL1));
            s_[nf][3] = exp2f(fmaf(s_[nf][3], L2E, -nmL1));
        }

        // per-lane partial sums (quad-reduce deferred to epilogue; cr is quad-uniform)
        float u0 = (s_[0][0] + s_[0][1]) + (s_[1][0] + s_[1][1]);
        float u1 = (s_[2][0] + s_[2][1]) + (s_[3][0] + s_[3][1]);
        float u2 = (s_[4][0] + s_[4][1]) + (s_[5][0] + s_[5][1]);
        float u3 = (s_[6][0] + s_[6][1]) + (s_[7][0] + s_[7][1]);
        float w0 = (s_[0][2] + s_[0][3]) + (s_[1][2] + s_[1][3]);
        float w1 = (s_[2][2] + s_[2][3]) + (s_[3][2] + s_[3][3]);
        float w2 = (s_[4][2] + s_[4][3]) + (s_[5][2] + s_[5][3]);
        float w3 = (s_[6][2] + s_[6][3]) + (s_[7][2] + s_[7][3]);
        l0 = l0 * cr0 + ((u0 + u1) + (u2 + u3));
        l1 = l1 * cr1 + ((w0 + w1) + (w2 + w3));

        // ---- pack P -> fp16 A fragments ----
        uint32_t ph_[4][4];
        #pragma unroll
        for (int st = 0; st < 4; st++) {
            ph_[st][0] = packh2(s_[2 * st][0],     s_[2 * st][1]);
            ph_[st][1] = packh2(s_[2 * st][2],     s_[2 * st][3]);
            ph_[st][2] = packh2(s_[2 * st + 1][0], s_[2 * st + 1][1]);
            ph_[st][3] = packh2(s_[2 * st + 1][2], s_[2 * st + 1][3]);
        }

        // ---- O += P*V (fp16 x1) ----
        #pragma unroll
        for (int st = 0; st < 4; st++) {
            #pragma unroll
            for (int g = 0; g < 4; g++) {
                uint32_t off = sw128((uint32_t)((16 * st + vrow) * 128 + (2 * g + vseg) * 16));
                uint32_t b0, b1, b2, b3;
                ldsm4t(b0, b1, b2, b3, cur + AO_VF + off);
                mmafp(o_[2 * g], ph_[st], b0, b1);
                mmafp(o_[2 * g + 1], ph_[st], b2, b3);
            }
        }
    }

    // ---- epilogue: quad-reduce l, normalize, write fp16 ctx ----
    l0 += __shfl_xor_sync(0xffffffffu, l0, 1);
    l0 += __shfl_xor_sync(0xffffffffu, l0, 2);
    l1 += __shfl_xor_sync(0xffffffffu, l1, 1);
    l1 += __shfl_xor_sync(0xffffffffu, l1, 2);
    float inv0 = 1.0f / l0, inv1 = 1.0f / l1;
    int r0 = q0 + 16 * w + (l >> 2);
    size_t base0 = ((size_t)b * T1 + r0) * HID + h * DH;
    size_t base1 = base0 + (size_t)8 * HID;
    #pragma unroll
    for (int nf = 0; nf < 8; nf++) {
        int col = 8 * nf + 2 * (l & 3);
        *(uint32_t*)(g_ch + base0 + col) = packh2(o_[nf][0] * inv0, o_[nf][1] * inv0);
        *(uint32_t*)(g_ch + base1 + col) = packh2(o_[nf][2] * inv1, o_[nf][3] * inv1);
    }
}

// ---------------- proj: 512 threads, 128x128 CTA, 32x32 warp tiles, 3-stage ----------------
#define PB_A  0
#define PB_W  16384
#define PB_SZ 32768
#define PROJ_SMEM (3 * PB_SZ + 1024)

__device__ __forceinline__ void proj_issue(uint32_t sbuf, int r0c, int n0, int e0, int tid)
{
    #pragma unroll
    for (int j = 0; j < 2; j++) {
        int i = tid * 2 + j;
        int row = i >> 3, seg = i & 7;
        uint32_t dsw = sw128((uint32_t)(row * 128 + seg * 16));
        size_t ra = (size_t)(r0c + row) * HID + e0 + seg * 8;
        size_t rw = (size_t)(n0 + row) * HID + e0 + seg * 8;
        CP16(sbuf + PB_A + dsw, g_ch + ra);
        CP16(sbuf + PB_W + dsw, g_wf + rw);
    }
}

__global__ __launch_bounds__(512, 2) void proj_tc(const float* __restrict__ bias,
                                                  float* __restrict__ out)
{
    extern __shared__ char smraw[];
    uint32_t sb0 = smem_u32(smraw);
    uint32_t pad = (1024u - (sb0 & 1023u)) & 1023u;
    uint32_t sb = sb0 + pad;

    const int tid = threadIdx.x;
    const int w = tid >> 5, l = tid & 31;
    const int wr = w >> 2, wc = w & 3;           // warp tile: rows 32*wr, cols 32*wc
    const int r0c = blockIdx.x * 128, n0 = blockIdx.y * 128;

    const uint32_t aseg = (uint32_t)(l >> 4);
    const uint32_t krow = (uint32_t)((l & 7) + ((l & 16) >> 1));
    const uint32_t kseg = (uint32_t)((l >> 3) & 1);

    float acc[8][4];   // [mf*4 + 2*g + half]
    #pragma unroll
    for (int i = 0; i < 8; i++)
        #pragma unroll
        for (int j = 0; j < 4; j++) acc[i][j] = 0.f;

    proj_issue(sb, r0c, n0, 0, tid);
    CP_COMMIT();
    proj_issue(sb + PB_SZ, r0c, n0, 64, tid);
    CP_COMMIT();

    int cb = 0;
    for (int c = 0; c < 16; c++) {
        CP_WAIT1();
        __syncthreads();
        if (c + 2 < 16) {
            int ib = cb + 2; if (ib >= 3) ib -= 3;
            proj_issue(sb + (uint32_t)ib * PB_SZ, r0c, n0, (c + 2) * 64, tid);
            CP_COMMIT();
        }
        uint32_t cur = sb + (uint32_t)cb * PB_SZ;
        cb = (cb == 2) ? 0 : cb + 1;

        #pragma unroll
        for (int st = 0; st < 4; st++) {
            uint32_t a0_[4], a1_[4];
            {
                uint32_t ar = (uint32_t)(32 * wr + (l & 15));
                ldsm4(a0_[0], a0_[1], a0_[2], a0_[3],
                      cur + PB_A + sw128(ar * 128 + (uint32_t)(2 * st + aseg) * 16));
                ldsm4(a1_[0], a1_[1], a1_[2], a1_[3],
                      cur + PB_A + sw128((ar + 16) * 128 + (uint32_t)(2 * st + aseg) * 16));
            }
            #pragma unroll
            for (int g = 0; g < 2; g++) {
                uint32_t wrow = (uint32_t)(32 * wc + 16 * g) + krow;
                uint32_t off = sw128(wrow * 128 + (uint32_t)(2 * st + kseg) * 16);
                uint32_t b0, b1, b2, b3;
                ldsm4(b0, b1, b2, b3, cur + PB_W + off);
                mmafp(acc[2 * g],         a0_, b0, b1);
                mmafp(acc[2 * g + 1],     a0_, b2, b3);
                mmafp(acc[4 + 2 * g],     a1_, b0, b1);
                mmafp(acc[4 + 2 * g + 1], a1_, b2, b3);
            }
        }
    }

    // epilogue: +bias, relu
    #pragma unroll
    for (int mf = 0; mf < 2; mf++) {
        int row0 = r0c + 32 * wr + 16 * mf + (l >> 2);
        #pragma unroll
        for (int nf = 0; nf < 4; nf++) {
            int col = n0 + 32 * wc + 8 * nf + 2 * (l & 3);
            float bx = bias[col], by = bias[col + 1];
            const float* a = acc[mf * 4 + nf];
            float2 t0 = make_float2(fmaxf(a[0] + bx, 0.f), fmaxf(a[1] + by, 0.f));
            float2 t1 = make_float2(fmaxf(a[2] + bx, 0.f), fmaxf(a[3] + by, 0.f));
            *(float2*)(out + (size_t)row0 * HID + col) = t0;
            *(float2*)(out + (size_t)(row0 + 8) * HID + col) = t1;
        }
    }
}

// ---------------- launch ----------------
extern "C" void kernel_launch(void* const* d_in, const int* in_sizes, int n_in,
                              void* d_out, int out_size)
{
    const float* q    = (const float*)d_in[0];
    const float* ek   = (const float*)d_in[1];
    const float* ev   = (const float*)d_in[2];
    const float* mask = (const float*)d_in[3];
    const float* wo_w = (const float*)d_in[4];
    const float* wo_b = (const float*)d_in[5];
    float* out = (float*)d_out;

    cudaFuncSetAttribute(attn_tc, cudaFuncAttributeMaxDynamicSharedMemorySize, ATT_SMEM);
    cudaFuncSetAttribute(proj_tc, cudaFuncAttributeMaxDynamicSharedMemorySize, PROJ_SMEM);

    zero_flag_k<<<1, 1>>>();

    dim3 gPr(512, 5);
    prep_k<<<gPr, 256>>>(q, ek, ev, wo_w, mask);

    dim3 gA(T1 / 128, BH);
    attn_tc<<<gA, 256, ATT_SMEM>>>(mask);

    dim3 gP(NB * T1 / 128, HID / 128);
    proj_tc<<<gP, 512, PROJ_SMEM>>>(wo_b, out);
}